// round 2
// baseline (speedup 1.0000x reference)
#include <cuda_runtime.h>

#define LRELU_ALPHA 0.2f
#define NEGINF (-9.0e15f)

#define BATCH 8
#define NNODE 2048
#define FIN   256
#define FOUT  128

// Scratch (device globals: allocation-free per harness rules)
static __device__ float g_h[BATCH * NNODE * FOUT];    // 8.4 MB
static __device__ float g_f1[BATCH * NNODE];
static __device__ float g_f2[BATCH * NNODE];

// ---------- packed f32x2 helpers ----------
__device__ __forceinline__ unsigned long long pk2(float a, float b) {
    unsigned long long r;
    asm("mov.b64 %0, {%1,%2};" : "=l"(r) : "f"(a), "f"(b));
    return r;
}
__device__ __forceinline__ void upk2(unsigned long long v, float& a, float& b) {
    asm("mov.b64 {%0,%1}, %2;" : "=f"(a), "=f"(b) : "l"(v));
}
__device__ __forceinline__ unsigned long long ffma2(unsigned long long a,
                                                    unsigned long long b,
                                                    unsigned long long c) {
    unsigned long long d;
    asm("fma.rn.f32x2 %0, %1, %2, %3;" : "=l"(d) : "l"(a), "l"(b), "l"(c));
    return d;
}

// ============================================================
// Kernel 1: h = x @ W ; f1 = h @ a1 ; f2 = h @ a2  (unchanged, at floor)
// ============================================================
__global__ void __launch_bounds__(256) k_gemm(const float* __restrict__ x,
                                              const float* __restrict__ W,
                                              const float* __restrict__ a) {
    __shared__ float xs[64][32];
    __shared__ float ws[32][128];
    const int t = threadIdx.x;
    const int row0 = blockIdx.x * 64;
    const int c4 = (t & 31) * 4;
    const int rg = t >> 5;

    unsigned long long acc[8][2];
#pragma unroll
    for (int r = 0; r < 8; r++) { acc[r][0] = 0ULL; acc[r][1] = 0ULL; }

    for (int k0 = 0; k0 < FIN; k0 += 32) {
        {
            const int rr = t >> 3;
            const int cc = (t & 7) * 4;
            float4 v0 = *reinterpret_cast<const float4*>(&x[(size_t)(row0 + rr) * FIN + k0 + cc]);
            float4 v1 = *reinterpret_cast<const float4*>(&x[(size_t)(row0 + rr + 32) * FIN + k0 + cc]);
            *reinterpret_cast<float4*>(&xs[rr][cc]) = v0;
            *reinterpret_cast<float4*>(&xs[rr + 32][cc]) = v1;
        }
        {
            const int kr = t >> 5;
            const int cc = (t & 31) * 4;
#pragma unroll
            for (int i = 0; i < 4; i++) {
                float4 v = *reinterpret_cast<const float4*>(&W[(size_t)(k0 + kr + i * 8) * FOUT + cc]);
                *reinterpret_cast<float4*>(&ws[kr + i * 8][cc]) = v;
            }
        }
        __syncthreads();
#pragma unroll
        for (int k = 0; k < 32; k++) {
            ulonglong2 wv = *reinterpret_cast<const ulonglong2*>(&ws[k][c4]);
#pragma unroll
            for (int r = 0; r < 8; r++) {
                float xv = xs[rg * 8 + r][k];
                unsigned long long xd = pk2(xv, xv);
                acc[r][0] = ffma2(xd, wv.x, acc[r][0]);
                acc[r][1] = ffma2(xd, wv.y, acc[r][1]);
            }
        }
        __syncthreads();
    }

    float4 a1 = *reinterpret_cast<const float4*>(&a[c4]);
    float4 a2 = *reinterpret_cast<const float4*>(&a[FOUT + c4]);
#pragma unroll
    for (int r = 0; r < 8; r++) {
        float h0, h1, h2, h3;
        upk2(acc[r][0], h0, h1);
        upk2(acc[r][1], h2, h3);
        const int grow = row0 + rg * 8 + r;
        *reinterpret_cast<float4*>(&g_h[(size_t)grow * FOUT + c4]) = make_float4(h0, h1, h2, h3);
        float s1 = h0 * a1.x + h1 * a1.y + h2 * a1.z + h3 * a1.w;
        float s2 = h0 * a2.x + h1 * a2.y + h2 * a2.z + h3 * a2.w;
#pragma unroll
        for (int off = 16; off; off >>= 1) {
            s1 += __shfl_xor_sync(0xffffffffu, s1, off);
            s2 += __shfl_xor_sync(0xffffffffu, s2, off);
        }
        if ((t & 31) == 0) { g_f1[grow] = s1; g_f2[grow] = s2; }
    }
}

// ============================================================
// Kernel 2: fused masked-softmax attention + att @ h + ELU
// No online max (unnormalized exp is safe: |e| <~ 8), lane-local l sum,
// single final reduction. 2 warps x 16 rows. p stored as duplicated (p,p)
// pairs so one LDS.128 broadcast feeds 4 FFMA2.
// ============================================================
#define JT 32
#define RW 16
#define NW 2
#define PSTRIDE 36   // 144B row stride: 16B-aligned, low STS conflict

__global__ void __launch_bounds__(64, 5) k_attn(const int* __restrict__ adj,
                                                float* __restrict__ out) {
    __shared__ float hs[2][JT][FOUT];          // 32 KB
    __shared__ float pdd[NW][JT][PSTRIDE];     // 9 KB, (p,p) interleaved pairs

    const int tid = threadIdx.x;
    const int w = tid >> 5, lane = tid & 31;
    const int b = blockIdx.y;
    const int row0 = blockIdx.x * (NW * RW);
    const int wrow0 = row0 + w * RW;
    const int* adjB = adj + (size_t)b * NNODE * NNODE;
    const float* hB = g_h + (size_t)b * NNODE * FOUT;
    const int lane4 = lane * 4;

    float f1r[RW];
#pragma unroll
    for (int r = 0; r < RW; r++) f1r[r] = g_f1[b * NNODE + wrow0 + r];

    float l[RW];
    unsigned long long acc[RW][2];
#pragma unroll
    for (int r = 0; r < RW; r++) { l[r] = 0.f; acc[r][0] = 0ULL; acc[r][1] = 0ULL; }

    auto stage = [&](int tile) {
        const int buf = tile & 1;
        const float* src = hB + (size_t)tile * JT * FOUT;
#pragma unroll
        for (int k = 0; k < 16; k++) {
            int idx = tid + k * 64;                  // float4 index 0..1023
            int rr = idx >> 5, cc = (idx & 31) * 4;
            unsigned sm = (unsigned)__cvta_generic_to_shared(&hs[buf][rr][cc]);
            asm volatile("cp.async.cg.shared.global [%0], [%1], 16;"
                         :: "r"(sm), "l"(src + rr * FOUT + cc));
        }
        asm volatile("cp.async.commit_group;");
    };

    stage(0);

    // prefetch adj bitmask + f2 for tile 0
    unsigned mCur = 0;
    float f2Cur;
    {
        const int j = lane;
#pragma unroll
        for (int r = 0; r < RW; r++)
            mCur |= (adjB[(size_t)(wrow0 + r) * NNODE + j] > 0) ? (1u << r) : 0u;
        f2Cur = g_f2[b * NNODE + j];
    }

    const int NT = NNODE / JT;   // 64
    for (int t = 0; t < NT; t++) {
        if (t + 1 < NT) {
            stage(t + 1);
            asm volatile("cp.async.wait_group 1;");
        } else {
            asm volatile("cp.async.wait_group 0;");
        }
        __syncthreads();

        // prefetch next adj tile (hides HBM latency under FFMA work)
        unsigned mNext = 0;
        float f2Next = 0.f;
        if (t + 1 < NT) {
            const int j = (t + 1) * JT + lane;
#pragma unroll
            for (int r = 0; r < RW; r++)
                mNext |= (adjB[(size_t)(wrow0 + r) * NNODE + j] > 0) ? (1u << r) : 0u;
            f2Next = g_f2[b * NNODE + j];
        }

        // p = exp(mask ? lrelu(f1+f2) : -inf), lane-local l accumulation.
        // No shuffles, no rescaling.
#pragma unroll
        for (int r = 0; r < RW; r++) {
            float tt = f1r[r] + f2Cur;
            float e = fmaxf(tt, LRELU_ALPHA * tt);    // leaky relu
            e = (mCur & (1u << r)) ? e : NEGINF;
            float pv = __expf(e);
            l[r] += pv;
            *reinterpret_cast<unsigned long long*>(&pdd[w][lane][2 * r]) = pk2(pv, pv);
        }
        __syncwarp();

        // acc += p * h : FFMA2-dominant inner loop
        const int buf = t & 1;
#pragma unroll 16
        for (int jj = 0; jj < JT; jj++) {
            ulonglong2 hv = *reinterpret_cast<const ulonglong2*>(&hs[buf][jj][lane4]);
#pragma unroll
            for (int k = 0; k < RW / 2; k++) {
                ulonglong2 pp = *reinterpret_cast<const ulonglong2*>(&pdd[w][jj][4 * k]);
                acc[2 * k][0]     = ffma2(pp.x, hv.x, acc[2 * k][0]);
                acc[2 * k][1]     = ffma2(pp.x, hv.y, acc[2 * k][1]);
                acc[2 * k + 1][0] = ffma2(pp.y, hv.x, acc[2 * k + 1][0]);
                acc[2 * k + 1][1] = ffma2(pp.y, hv.y, acc[2 * k + 1][1]);
            }
        }
        __syncthreads();
        mCur = mNext;
        f2Cur = f2Next;
    }

    // epilogue: single reduction of l per row, normalize, ELU, store
#pragma unroll
    for (int r = 0; r < RW; r++) {
        float sl = l[r];
#pragma unroll
        for (int off = 16; off; off >>= 1)
            sl += __shfl_xor_sync(0xffffffffu, sl, off);
        float inv = 1.0f / sl;
        float v0, v1, v2, v3;
        upk2(acc[r][0], v0, v1);
        upk2(acc[r][1], v2, v3);
        v0 *= inv; v1 *= inv; v2 *= inv; v3 *= inv;
        v0 = v0 > 0.f ? v0 : expm1f(v0);
        v1 = v1 > 0.f ? v1 : expm1f(v1);
        v2 = v2 > 0.f ? v2 : expm1f(v2);
        v3 = v3 > 0.f ? v3 : expm1f(v3);
        *reinterpret_cast<float4*>(
            &out[(size_t)(b * NNODE + wrow0 + r) * FOUT + lane4]) =
            make_float4(v0, v1, v2, v3);
    }
}

// ============================================================
extern "C" void kernel_launch(void* const* d_in, const int* in_sizes, int n_in,
                              void* d_out, int out_size) {
    const float* x   = (const float*)d_in[0];   // (8, 2048, 256) f32
    const int*   adj = (const int*)d_in[1];     // (8, 2048, 2048) i32
    const float* W   = (const float*)d_in[2];   // (256, 128) f32
    const float* a   = (const float*)d_in[3];   // (256, 1) f32
    float* out = (float*)d_out;                 // (8, 2048, 128) f32

    k_gemm<<<(BATCH * NNODE) / 64, 256>>>(x, W, a);
    dim3 grid(NNODE / (NW * RW), BATCH);
    k_attn<<<grid, 64>>>(adj, out);
}

// round 5
// speedup vs baseline: 1.6459x; 1.6459x over previous
#include <cuda_runtime.h>

#define LRELU_ALPHA 0.2f
#define NEGINF (-9.0e15f)

#define BATCH 8
#define NNODE 2048
#define FIN   256
#define FOUT  128

// Scratch (device globals: allocation-free per harness rules)
static __device__ float g_h[BATCH * NNODE * FOUT];    // 8.4 MB
static __device__ float g_f1[BATCH * NNODE];
static __device__ float g_f2[BATCH * NNODE];

// ---------- packed f32x2 helpers ----------
__device__ __forceinline__ unsigned long long pk2(float a, float b) {
    unsigned long long r;
    asm("mov.b64 %0, {%1,%2};" : "=l"(r) : "f"(a), "f"(b));
    return r;
}
__device__ __forceinline__ void upk2(unsigned long long v, float& a, float& b) {
    asm("mov.b64 {%0,%1}, %2;" : "=f"(a), "=f"(b) : "l"(v));
}
__device__ __forceinline__ unsigned long long ffma2(unsigned long long a,
                                                    unsigned long long b,
                                                    unsigned long long c) {
    unsigned long long d;
    asm("fma.rn.f32x2 %0, %1, %2, %3;" : "=l"(d) : "l"(a), "l"(b), "l"(c));
    return d;
}

// ============================================================
// Kernel 1: h = x @ W ; f1 = h @ a1 ; f2 = h @ a2  (unchanged)
// ============================================================
__global__ void __launch_bounds__(256) k_gemm(const float* __restrict__ x,
                                              const float* __restrict__ W,
                                              const float* __restrict__ a) {
    __shared__ float xs[64][32];
    __shared__ float ws[32][128];
    const int t = threadIdx.x;
    const int row0 = blockIdx.x * 64;
    const int c4 = (t & 31) * 4;
    const int rg = t >> 5;

    unsigned long long acc[8][2];
#pragma unroll
    for (int r = 0; r < 8; r++) { acc[r][0] = 0ULL; acc[r][1] = 0ULL; }

    for (int k0 = 0; k0 < FIN; k0 += 32) {
        {
            const int rr = t >> 3;
            const int cc = (t & 7) * 4;
            float4 v0 = *reinterpret_cast<const float4*>(&x[(size_t)(row0 + rr) * FIN + k0 + cc]);
            float4 v1 = *reinterpret_cast<const float4*>(&x[(size_t)(row0 + rr + 32) * FIN + k0 + cc]);
            *reinterpret_cast<float4*>(&xs[rr][cc]) = v0;
            *reinterpret_cast<float4*>(&xs[rr + 32][cc]) = v1;
        }
        {
            const int kr = t >> 5;
            const int cc = (t & 31) * 4;
#pragma unroll
            for (int i = 0; i < 4; i++) {
                float4 v = *reinterpret_cast<const float4*>(&W[(size_t)(k0 + kr + i * 8) * FOUT + cc]);
                *reinterpret_cast<float4*>(&ws[kr + i * 8][cc]) = v;
            }
        }
        __syncthreads();
#pragma unroll
        for (int k = 0; k < 32; k++) {
            ulonglong2 wv = *reinterpret_cast<const ulonglong2*>(&ws[k][c4]);
#pragma unroll
            for (int r = 0; r < 8; r++) {
                float xv = xs[rg * 8 + r][k];
                unsigned long long xd = pk2(xv, xv);
                acc[r][0] = ffma2(xd, wv.x, acc[r][0]);
                acc[r][1] = ffma2(xd, wv.y, acc[r][1]);
            }
        }
        __syncthreads();
    }

    float4 a1 = *reinterpret_cast<const float4*>(&a[c4]);
    float4 a2 = *reinterpret_cast<const float4*>(&a[FOUT + c4]);
#pragma unroll
    for (int r = 0; r < 8; r++) {
        float h0, h1, h2, h3;
        upk2(acc[r][0], h0, h1);
        upk2(acc[r][1], h2, h3);
        const int grow = row0 + rg * 8 + r;
        *reinterpret_cast<float4*>(&g_h[(size_t)grow * FOUT + c4]) = make_float4(h0, h1, h2, h3);
        float s1 = h0 * a1.x + h1 * a1.y + h2 * a1.z + h3 * a1.w;
        float s2 = h0 * a2.x + h1 * a2.y + h2 * a2.z + h3 * a2.w;
#pragma unroll
        for (int off = 16; off; off >>= 1) {
            s1 += __shfl_xor_sync(0xffffffffu, s1, off);
            s2 += __shfl_xor_sync(0xffffffffu, s2, off);
        }
        if ((t & 31) == 0) { g_f1[grow] = s1; g_f2[grow] = s2; }
    }
}

// ============================================================
// Kernel 2: fused masked-softmax attention + att @ h + ELU
// 4 warps x 8 rows (R1 occupancy shape) + shuffle-free unnormalized
// softmax (R2 math: |e| <~ 8 so exp never overflows; lane-local l,
// one final reduce). p stored as duplicated (p,p) pairs; paired
// LDS.128 feeds 4 FFMA2 per load.
// ============================================================
#define JT 32
#define RW 8
#define NW 4
#define PSTRIDE 20   // floats; 80B row stride, 16B aligned

__global__ void __launch_bounds__(128, 4) k_attn(const int* __restrict__ adj,
                                                 float* __restrict__ out) {
    __shared__ float hs[2][JT][FOUT];          // 32 KB
    __shared__ float pdd[NW][JT][PSTRIDE];     // 10 KB

    const int tid = threadIdx.x;
    const int w = tid >> 5, lane = tid & 31;
    const int b = blockIdx.y;
    const int row0 = blockIdx.x * (NW * RW);
    const int wrow0 = row0 + w * RW;
    const int* adjB = adj + (size_t)b * NNODE * NNODE;
    const float* hB = g_h + (size_t)b * NNODE * FOUT;
    const int lane4 = lane * 4;

    float f1r[RW];
#pragma unroll
    for (int r = 0; r < RW; r++) f1r[r] = g_f1[b * NNODE + wrow0 + r];

    float l[RW];
    unsigned long long acc[RW][2];
#pragma unroll
    for (int r = 0; r < RW; r++) { l[r] = 0.f; acc[r][0] = 0ULL; acc[r][1] = 0ULL; }

    auto stage = [&](int tile) {
        const int buf = tile & 1;
        const float* src = hB + (size_t)tile * JT * FOUT;
#pragma unroll
        for (int k = 0; k < 8; k++) {
            int idx = tid + k * 128;                 // float4 index 0..1023
            int rr = idx >> 5, cc = (idx & 31) * 4;
            unsigned sm = (unsigned)__cvta_generic_to_shared(&hs[buf][rr][cc]);
            asm volatile("cp.async.cg.shared.global [%0], [%1], 16;"
                         :: "r"(sm), "l"(src + rr * FOUT + cc));
        }
        asm volatile("cp.async.commit_group;");
    };

    stage(0);

    // prefetch adj bitmask + f2 for tile 0
    unsigned mCur = 0;
    float f2Cur;
    {
        const int j = lane;
#pragma unroll
        for (int r = 0; r < RW; r++)
            mCur |= (adjB[(size_t)(wrow0 + r) * NNODE + j] > 0) ? (1u << r) : 0u;
        f2Cur = g_f2[b * NNODE + j];
    }

    const int NT = NNODE / JT;   // 64
    for (int t = 0; t < NT; t++) {
        if (t + 1 < NT) {
            stage(t + 1);
            asm volatile("cp.async.wait_group 1;");
        } else {
            asm volatile("cp.async.wait_group 0;");
        }
        __syncthreads();

        // prefetch next adj tile (hidden under FFMA work)
        unsigned mNext = 0;
        float f2Next = 0.f;
        if (t + 1 < NT) {
            const int j = (t + 1) * JT + lane;
#pragma unroll
            for (int r = 0; r < RW; r++)
                mNext |= (adjB[(size_t)(wrow0 + r) * NNODE + j] > 0) ? (1u << r) : 0u;
            f2Next = g_f2[b * NNODE + j];
        }

        // p = exp(mask ? lrelu(f1+f2) : -inf); lane-local l. No shuffles.
#pragma unroll
        for (int r = 0; r < RW; r++) {
            float tt = f1r[r] + f2Cur;
            float e = fmaxf(tt, LRELU_ALPHA * tt);
            e = (mCur & (1u << r)) ? e : NEGINF;
            float pv = __expf(e);
            l[r] += pv;
            *reinterpret_cast<unsigned long long*>(&pdd[w][lane][2 * r]) = pk2(pv, pv);
        }
        __syncwarp();

        // acc += p * h : FFMA2-dominant inner loop
        const int buf = t & 1;
#pragma unroll 8
        for (int jj = 0; jj < JT; jj++) {
            ulonglong2 hv = *reinterpret_cast<const ulonglong2*>(&hs[buf][jj][lane4]);
#pragma unroll
            for (int k = 0; k < RW / 2; k++) {
                ulonglong2 pp = *reinterpret_cast<const ulonglong2*>(&pdd[w][jj][4 * k]);
                acc[2 * k][0]     = ffma2(pp.x, hv.x, acc[2 * k][0]);
                acc[2 * k][1]     = ffma2(pp.x, hv.y, acc[2 * k][1]);
                acc[2 * k + 1][0] = ffma2(pp.y, hv.x, acc[2 * k + 1][0]);
                acc[2 * k + 1][1] = ffma2(pp.y, hv.y, acc[2 * k + 1][1]);
            }
        }
        __syncthreads();
        mCur = mNext;
        f2Cur = f2Next;
    }

    // epilogue: single reduce of l per row, normalize, ELU, store
#pragma unroll
    for (int r = 0; r < RW; r++) {
        float sl = l[r];
#pragma unroll
        for (int off = 16; off; off >>= 1)
            sl += __shfl_xor_sync(0xffffffffu, sl, off);
        float inv = 1.0f / sl;
        float v0, v1, v2, v3;
        upk2(acc[r][0], v0, v1);
        upk2(acc[r][1], v2, v3);
        v0 *= inv; v1 *= inv; v2 *= inv; v3 *= inv;
        v0 = v0 > 0.f ? v0 : expm1f(v0);
        v1 = v1 > 0.f ? v1 : expm1f(v1);
        v2 = v2 > 0.f ? v2 : expm1f(v2);
        v3 = v3 > 0.f ? v3 : expm1f(v3);
        *reinterpret_cast<float4*>(
            &out[(size_t)(b * NNODE + wrow0 + r) * FOUT + lane4]) =
            make_float4(v0, v1, v2, v3);
    }
}

// ============================================================
extern "C" void kernel_launch(void* const* d_in, const int* in_sizes, int n_in,
                              void* d_out, int out_size) {
    const float* x   = (const float*)d_in[0];   // (8, 2048, 256) f32
    const int*   adj = (const int*)d_in[1];     // (8, 2048, 2048) i32
    const float* W   = (const float*)d_in[2];   // (256, 128) f32
    const float* a   = (const float*)d_in[3];   // (256, 1) f32
    float* out = (float*)d_out;                 // (8, 2048, 128) f32

    k_gemm<<<(BATCH * NNODE) / 64, 256>>>(x, W, a);
    dim3 grid(NNODE / (NW * RW), BATCH);
    k_attn<<<grid, 128>>>(adj, out);
}

// round 8
// speedup vs baseline: 2.8819x; 1.7509x over previous
#include <cuda_runtime.h>
#include <cstdint>

#define LRELU_ALPHA 0.2f
#define NEGINF (-9.0e15f)

#define BATCH 8
#define NNODE 2048
#define FIN   256
#define FOUT  128

// ---------------- scratch (device globals) ----------------
static __device__ float    g_f1[BATCH * NNODE];
static __device__ float    g_f2[BATCH * NNODE];
// split-bf16 h: each unsigned holds 2 bf16 (cols 2k, 2k+1). Layout [b*N + j][64]
static __device__ unsigned g_hh[BATCH * NNODE * (FOUT / 2)];   // high parts
static __device__ unsigned g_hl[BATCH * NNODE * (FOUT / 2)];   // residuals

// ---------------- helpers ----------------
__device__ __forceinline__ unsigned smem_u32(const void* p) {
    unsigned a;
    asm("{ .reg .u64 t; cvta.to.shared.u64 t, %1; cvt.u32.u64 %0, t; }" : "=r"(a) : "l"(p));
    return a;
}
#define SW128(off) ((off) ^ (((off) >> 3) & 0x70))

// cvt: lo-half = a, hi-half = b
#define CVT_BF16X2(res, a, b) \
    asm("cvt.rn.satfinite.bf16x2.f32 %0, %1, %2;" : "=r"(res) : "f"(b), "f"(a))

__device__ __forceinline__ unsigned long long pk2(float a, float b) {
    unsigned long long r;
    asm("mov.b64 %0, {%1,%2};" : "=l"(r) : "f"(a), "f"(b));
    return r;
}
__device__ __forceinline__ void upk2(unsigned long long v, float& a, float& b) {
    asm("mov.b64 {%0,%1}, %2;" : "=f"(a), "=f"(b) : "l"(v));
}
__device__ __forceinline__ unsigned long long ffma2(unsigned long long a,
                                                    unsigned long long b,
                                                    unsigned long long c) {
    unsigned long long d;
    asm("fma.rn.f32x2 %0, %1, %2, %3;" : "=l"(d) : "l"(a), "l"(b), "l"(c));
    return d;
}

__device__ __forceinline__ void ldsm_x4(unsigned& r0, unsigned& r1, unsigned& r2,
                                        unsigned& r3, unsigned addr) {
    asm volatile("ldmatrix.sync.aligned.m8n8.x4.shared.b16 {%0,%1,%2,%3}, [%4];"
                 : "=r"(r0), "=r"(r1), "=r"(r2), "=r"(r3) : "r"(addr));
}
__device__ __forceinline__ void ldsm_x4_t(unsigned& r0, unsigned& r1, unsigned& r2,
                                          unsigned& r3, unsigned addr) {
    asm volatile("ldmatrix.sync.aligned.m8n8.x4.trans.shared.b16 {%0,%1,%2,%3}, [%4];"
                 : "=r"(r0), "=r"(r1), "=r"(r2), "=r"(r3) : "r"(addr));
}
__device__ __forceinline__ void mma_bf16(float* c, const unsigned* a,
                                         unsigned b0, unsigned b1) {
    asm volatile(
        "mma.sync.aligned.m16n8k16.row.col.f32.bf16.bf16.f32 "
        "{%0,%1,%2,%3}, {%4,%5,%6,%7}, {%8,%9}, {%0,%1,%2,%3};"
        : "+f"(c[0]), "+f"(c[1]), "+f"(c[2]), "+f"(c[3])
        : "r"(a[0]), "r"(a[1]), "r"(a[2]), "r"(a[3]), "r"(b0), "r"(b1));
}

// ============================================================
// Kernel 1: h = x@W ; f1,f2 ; write split-bf16 h
// ============================================================
__global__ void __launch_bounds__(256) k_gemm(const float* __restrict__ x,
                                              const float* __restrict__ W,
                                              const float* __restrict__ a) {
    __shared__ float xs[64][32];
    __shared__ float ws[32][128];
    const int t = threadIdx.x;
    const int row0 = blockIdx.x * 64;
    const int c4 = (t & 31) * 4;
    const int rg = t >> 5;

    unsigned long long acc[8][2];
#pragma unroll
    for (int r = 0; r < 8; r++) { acc[r][0] = 0ULL; acc[r][1] = 0ULL; }

    for (int k0 = 0; k0 < FIN; k0 += 32) {
        {
            const int rr = t >> 3, cc = (t & 7) * 4;
            float4 v0 = *reinterpret_cast<const float4*>(&x[(size_t)(row0 + rr) * FIN + k0 + cc]);
            float4 v1 = *reinterpret_cast<const float4*>(&x[(size_t)(row0 + rr + 32) * FIN + k0 + cc]);
            *reinterpret_cast<float4*>(&xs[rr][cc]) = v0;
            *reinterpret_cast<float4*>(&xs[rr + 32][cc]) = v1;
        }
        {
            const int kr = t >> 5, cc = (t & 31) * 4;
#pragma unroll
            for (int i = 0; i < 4; i++) {
                float4 v = *reinterpret_cast<const float4*>(&W[(size_t)(k0 + kr + i * 8) * FOUT + cc]);
                *reinterpret_cast<float4*>(&ws[kr + i * 8][cc]) = v;
            }
        }
        __syncthreads();
#pragma unroll
        for (int k = 0; k < 32; k++) {
            ulonglong2 wv = *reinterpret_cast<const ulonglong2*>(&ws[k][c4]);
#pragma unroll
            for (int r = 0; r < 8; r++) {
                float xv = xs[rg * 8 + r][k];
                unsigned long long xd = pk2(xv, xv);
                acc[r][0] = ffma2(xd, wv.x, acc[r][0]);
                acc[r][1] = ffma2(xd, wv.y, acc[r][1]);
            }
        }
        __syncthreads();
    }

    float4 a1 = *reinterpret_cast<const float4*>(&a[c4]);
    float4 a2 = *reinterpret_cast<const float4*>(&a[FOUT + c4]);
#pragma unroll
    for (int r = 0; r < 8; r++) {
        float h0, h1, h2, h3;
        upk2(acc[r][0], h0, h1);
        upk2(acc[r][1], h2, h3);
        const int grow = row0 + rg * 8 + r;
        unsigned hi01, hi23, lo01, lo23;
        CVT_BF16X2(hi01, h0, h1);
        CVT_BF16X2(hi23, h2, h3);
        float q0 = __uint_as_float(hi01 << 16);
        float q1 = __uint_as_float(hi01 & 0xffff0000u);
        float q2 = __uint_as_float(hi23 << 16);
        float q3 = __uint_as_float(hi23 & 0xffff0000u);
        CVT_BF16X2(lo01, h0 - q0, h1 - q1);
        CVT_BF16X2(lo23, h2 - q2, h3 - q3);
        *reinterpret_cast<uint2*>(&g_hh[(size_t)grow * 64 + (c4 >> 1)]) = make_uint2(hi01, hi23);
        *reinterpret_cast<uint2*>(&g_hl[(size_t)grow * 64 + (c4 >> 1)]) = make_uint2(lo01, lo23);

        float s1 = h0 * a1.x + h1 * a1.y + h2 * a1.z + h3 * a1.w;
        float s2 = h0 * a2.x + h1 * a2.y + h2 * a2.z + h3 * a2.w;
#pragma unroll
        for (int off = 16; off; off >>= 1) {
            s1 += __shfl_xor_sync(0xffffffffu, s1, off);
            s2 += __shfl_xor_sync(0xffffffffu, s2, off);
        }
        if ((t & 31) == 0) { g_f1[grow] = s1; g_f2[grow] = s2; }
    }
}

// ============================================================
// Kernel 2: mma.sync (HMMA) fused attention.
// CTA = 64 rows x 128 F, 256 thr / 8 warps; warp = m16 x n64 slab.
// Register accumulators across all 32 j-tiles. P hi/lo built per tile
// into SW128 smem; H hi/lo staged via cp.async (2 bufs), consumed via
// ldmatrix.x4.trans as col-major B.
// ============================================================
#define JT2 64
#define NT2 (NNODE / JT2)           // 32

#define OFF_PHI 0                    // [64][128B] 8 KB
#define OFF_PLO 8192                 // 8 KB
#define OFF_H   16384                // 2 bufs x 32 KB: [hi h0][hi h1][lo h0][lo h1]
#define OFF_LROW (OFF_H + 65536)     // 64 floats
#define SMEM_ATTN (OFF_LROW + 256)

__global__ void __launch_bounds__(256, 2) k_attn(const int* __restrict__ adj,
                                                 float* __restrict__ out) {
    extern __shared__ char smem[];
    const unsigned sb = smem_u32(smem);
    const int tid = threadIdx.x;
    const int w = tid >> 5, lane = tid & 31;
    const int b = blockIdx.y;
    const int row0 = blockIdx.x * 64;

    // ---- MMA geometry for this warp ----
    const int mrow0 = (w & 3) * 16;          // warp's m-slab (local rows)
    const int nhalf = w >> 2;                // warp's F-half (64 cols)
    // A-ldmatrix per-thread offsets (non-trans): sub 0..3 -> (row, kcol) blocks
    const int asub = lane >> 3, ai = lane & 7;
    const int a_row = mrow0 + (asub & 1) * 8 + ai;
    const int a_kof = (asub >> 1) * 8;
    // B-ldmatrix per-thread offsets (trans): sub -> (krow, ncol) blocks
    const int b_krow = (asub & 1) * 8 + ai;
    const int b_nof = (asub >> 1) * 8;

    // ---- P-gen geometry ----
    const int prow = w * 8 + (lane >> 2);    // local row this thread generates
    const int jb0 = (lane & 3) * 2;          // j within 8-col sector
    const float f1r = g_f1[b * NNODE + row0 + prow];
    const int* adjRow = adj + ((size_t)(b * NNODE + row0 + prow)) * NNODE;
    const float* f2B = g_f2 + b * NNODE;
    const char* hhB = (const char*)g_hh + (size_t)(b * NNODE) * 256;
    const char* hlB = (const char*)g_hl + (size_t)(b * NNODE) * 256;

    float acc[8][4];
#pragma unroll
    for (int i = 0; i < 8; i++)
#pragma unroll
        for (int k = 0; k < 4; k++) acc[i][k] = 0.f;
    float lpart = 0.f;

    // ---- stage H (hi+lo) tile into buffer ----
    auto stage = [&](int t2) {
        const unsigned hb = sb + OFF_H + (t2 & 1) * 32768;
        const char* sh = hhB + (size_t)t2 * 64 * 256;
        const char* sl = hlB + (size_t)t2 * 64 * 256;
#pragma unroll
        for (int k = 0; k < 4; k++) {
            int idx = tid * 4 + k;           // 0..1023
            int row = idx >> 4, ch = idx & 15;
            int half = ch >> 3, c = ch & 7;
            unsigned swo = SW128((unsigned)(row * 128 + c * 16));
            unsigned dh = hb + half * 8192 + swo;
            unsigned dl = hb + 16384 + half * 8192 + swo;
            const char* gsrc = sh + row * 256 + half * 128 + c * 16;
            asm volatile("cp.async.cg.shared.global [%0], [%1], 16;" :: "r"(dh), "l"(gsrc));
            gsrc = sl + row * 256 + half * 128 + c * 16;
            asm volatile("cp.async.cg.shared.global [%0], [%1], 16;" :: "r"(dl), "l"(gsrc));
        }
        asm volatile("cp.async.commit_group;");
    };

    // ---- P-gen for tile t2 (exp softmax numerator, split bf16) ----
    auto pgen = [&](int t2) {
        const int jg = t2 * JT2;
#pragma unroll
        for (int jj = 0; jj < 8; jj++) {
            const int jl = jb0 + jj * 8;
            float2 f2v = *reinterpret_cast<const float2*>(f2B + jg + jl);
            uint2 av = *reinterpret_cast<const uint2*>(adjRow + jg + jl);
            float t1 = f1r + f2v.x;
            t1 = fmaxf(t1, LRELU_ALPHA * t1);
            t1 = av.x ? t1 : NEGINF;
            float t2f = f1r + f2v.y;
            t2f = fmaxf(t2f, LRELU_ALPHA * t2f);
            t2f = av.y ? t2f : NEGINF;
            float p1 = __expf(t1), p2 = __expf(t2f);
            lpart += p1 + p2;
            unsigned hi;
            CVT_BF16X2(hi, p1, p2);
            float q1 = __uint_as_float(hi << 16);
            float q2 = __uint_as_float(hi & 0xffff0000u);
            unsigned lo;
            CVT_BF16X2(lo, p1 - q1, p2 - q2);
            unsigned off = SW128((unsigned)(prow * 128 + jl * 2));
            asm volatile("st.shared.b32 [%0], %1;" :: "r"(sb + OFF_PHI + off), "r"(hi) : "memory");
            asm volatile("st.shared.b32 [%0], %1;" :: "r"(sb + OFF_PLO + off), "r"(lo) : "memory");
        }
    };

    stage(0);
    pgen(0);

    for (int t = 0; t < NT2; t++) {
        asm volatile("cp.async.wait_group 0;");   // H(t) resident
        __syncthreads();                          // P(t) visible everywhere

        // A fragments for all 4 k-steps, both precisions (P buf then free)
        unsigned PAh[4][4], PAl[4][4];
#pragma unroll
        for (int ks = 0; ks < 4; ks++) {
            unsigned off = SW128((unsigned)(a_row * 128 + (ks * 16 + a_kof) * 2));
            ldsm_x4(PAh[ks][0], PAh[ks][1], PAh[ks][2], PAh[ks][3], sb + OFF_PHI + off);
            ldsm_x4(PAl[ks][0], PAl[ks][1], PAl[ks][2], PAl[ks][3], sb + OFF_PLO + off);
        }
        __syncthreads();                          // P buf reusable

        if (t + 1 < NT2) { stage(t + 1); pgen(t + 1); }

        // MMA: 4 k-steps x 4 n16-blocks x (hi*hi + hi*lo + lo*hi)
        const unsigned hb = sb + OFF_H + (t & 1) * 32768 + nhalf * 8192;
#pragma unroll
        for (int ks = 0; ks < 4; ks++) {
            unsigned Bh[4][4], Bl[4][4];
#pragma unroll
            for (int nb = 0; nb < 4; nb++) {
                unsigned off = SW128(
                    (unsigned)((ks * 16 + b_krow) * 128 + (nb * 16 + b_nof) * 2));
                ldsm_x4_t(Bh[nb][0], Bh[nb][1], Bh[nb][2], Bh[nb][3], hb + off);
                ldsm_x4_t(Bl[nb][0], Bl[nb][1], Bl[nb][2], Bl[nb][3], hb + 16384 + off);
            }
#pragma unroll
            for (int nb = 0; nb < 4; nb++) {
                mma_bf16(acc[nb * 2],     PAh[ks], Bh[nb][0], Bh[nb][1]);
                mma_bf16(acc[nb * 2 + 1], PAh[ks], Bh[nb][2], Bh[nb][3]);
                mma_bf16(acc[nb * 2],     PAh[ks], Bl[nb][0], Bl[nb][1]);
                mma_bf16(acc[nb * 2 + 1], PAh[ks], Bl[nb][2], Bl[nb][3]);
                mma_bf16(acc[nb * 2],     PAl[ks], Bh[nb][0], Bh[nb][1]);
                mma_bf16(acc[nb * 2 + 1], PAl[ks], Bh[nb][2], Bh[nb][3]);
            }
        }
    }

    // ---- row sums: reduce 4 partials per row, publish to smem ----
#pragma unroll
    for (int off = 1; off <= 2; off <<= 1)
        lpart += __shfl_xor_sync(0xffffffffu, lpart, off);
    if ((lane & 3) == 0)
        *reinterpret_cast<float*>(smem + OFF_LROW + prow * 4) = lpart;
    __syncthreads();

    // ---- epilogue: normalize + ELU + store ----
    const int gid = lane >> 2, tig = lane & 3;
    const float inv0 = 1.0f / reinterpret_cast<float*>(smem + OFF_LROW)[mrow0 + gid];
    const float inv1 = 1.0f / reinterpret_cast<float*>(smem + OFF_LROW)[mrow0 + gid + 8];
    float* outB = out + ((size_t)(b * NNODE + row0)) * FOUT;
#pragma unroll
    for (int k = 0; k < 8; k++) {
        const int col = nhalf * 64 + (k >> 1) * 16 + (k & 1) * 8 + tig * 2;
        float v0 = acc[k][0] * inv0, v1 = acc[k][1] * inv0;
        float v2 = acc[k][2] * inv1, v3 = acc[k][3] * inv1;
        v0 = v0 > 0.f ? v0 : expm1f(v0);
        v1 = v1 > 0.f ? v1 : expm1f(v1);
        v2 = v2 > 0.f ? v2 : expm1f(v2);
        v3 = v3 > 0.f ? v3 : expm1f(v3);
        *reinterpret_cast<float2*>(&outB[(size_t)(mrow0 + gid) * FOUT + col]) =
            make_float2(v0, v1);
        *reinterpret_cast<float2*>(&outB[(size_t)(mrow0 + gid + 8) * FOUT + col]) =
            make_float2(v2, v3);
    }
}

// ============================================================
extern "C" void kernel_launch(void* const* d_in, const int* in_sizes, int n_in,
                              void* d_out, int out_size) {
    const float* x   = (const float*)d_in[0];   // (8, 2048, 256) f32
    const int*   adj = (const int*)d_in[1];     // (8, 2048, 2048) i32
    const float* W   = (const float*)d_in[2];   // (256, 128) f32
    const float* a   = (const float*)d_in[3];   // (256, 1) f32
    float* out = (float*)d_out;                 // (8, 2048, 128) f32

    cudaFuncSetAttribute(k_attn, cudaFuncAttributeMaxDynamicSharedMemorySize, SMEM_ATTN);

    k_gemm<<<(BATCH * NNODE) / 64, 256>>>(x, W, a);
    dim3 grid(NNODE / 64, BATCH);
    k_attn<<<grid, 256, SMEM_ATTN>>>(adj, out);
}

// round 9
// speedup vs baseline: 2.9500x; 1.0236x over previous
#include <cuda_runtime.h>
#include <cstdint>

#define LRELU_ALPHA 0.2f
#define NEGINF (-9.0e15f)

#define BATCH 8
#define NNODE 2048
#define FIN   256
#define FOUT  128

// ---------------- scratch (device globals) ----------------
static __device__ float    g_f1[BATCH * NNODE];
static __device__ float    g_f2[BATCH * NNODE];
// split-bf16 h: each unsigned holds 2 bf16 (cols 2k, 2k+1). Layout [b*N + j][64]
static __device__ unsigned g_hh[BATCH * NNODE * (FOUT / 2)];   // high parts
static __device__ unsigned g_hl[BATCH * NNODE * (FOUT / 2)];   // residuals

// ---------------- helpers ----------------
__device__ __forceinline__ unsigned smem_u32(const void* p) {
    unsigned a;
    asm("{ .reg .u64 t; cvta.to.shared.u64 t, %1; cvt.u32.u64 %0, t; }" : "=r"(a) : "l"(p));
    return a;
}
#define SW128(off) ((off) ^ (((off) >> 3) & 0x70))

// cvt: lo-half = a, hi-half = b
#define CVT_BF16X2(res, a, b) \
    asm("cvt.rn.satfinite.bf16x2.f32 %0, %1, %2;" : "=r"(res) : "f"(b), "f"(a))

__device__ __forceinline__ unsigned long long pk2(float a, float b) {
    unsigned long long r;
    asm("mov.b64 %0, {%1,%2};" : "=l"(r) : "f"(a), "f"(b));
    return r;
}
__device__ __forceinline__ void upk2(unsigned long long v, float& a, float& b) {
    asm("mov.b64 {%0,%1}, %2;" : "=f"(a), "=f"(b) : "l"(v));
}
__device__ __forceinline__ unsigned long long ffma2(unsigned long long a,
                                                    unsigned long long b,
                                                    unsigned long long c) {
    unsigned long long d;
    asm("fma.rn.f32x2 %0, %1, %2, %3;" : "=l"(d) : "l"(a), "l"(b), "l"(c));
    return d;
}

__device__ __forceinline__ void ldsm_x4(unsigned& r0, unsigned& r1, unsigned& r2,
                                        unsigned& r3, unsigned addr) {
    asm volatile("ldmatrix.sync.aligned.m8n8.x4.shared.b16 {%0,%1,%2,%3}, [%4];"
                 : "=r"(r0), "=r"(r1), "=r"(r2), "=r"(r3) : "r"(addr));
}
__device__ __forceinline__ void ldsm_x4_t(unsigned& r0, unsigned& r1, unsigned& r2,
                                          unsigned& r3, unsigned addr) {
    asm volatile("ldmatrix.sync.aligned.m8n8.x4.trans.shared.b16 {%0,%1,%2,%3}, [%4];"
                 : "=r"(r0), "=r"(r1), "=r"(r2), "=r"(r3) : "r"(addr));
}
__device__ __forceinline__ void mma_bf16(float* c, const unsigned* a,
                                         unsigned b0, unsigned b1) {
    asm volatile(
        "mma.sync.aligned.m16n8k16.row.col.f32.bf16.bf16.f32 "
        "{%0,%1,%2,%3}, {%4,%5,%6,%7}, {%8,%9}, {%0,%1,%2,%3};"
        : "+f"(c[0]), "+f"(c[1]), "+f"(c[2]), "+f"(c[3])
        : "r"(a[0]), "r"(a[1]), "r"(a[2]), "r"(a[3]), "r"(b0), "r"(b1));
}

// ============================================================
// Kernel 1: h = x@W ; f1,f2 ; write split-bf16 h
// ============================================================
__global__ void __launch_bounds__(256) k_gemm(const float* __restrict__ x,
                                              const float* __restrict__ W,
                                              const float* __restrict__ a) {
    __shared__ float xs[64][32];
    __shared__ float ws[32][128];
    const int t = threadIdx.x;
    const int row0 = blockIdx.x * 64;
    const int c4 = (t & 31) * 4;
    const int rg = t >> 5;

    unsigned long long acc[8][2];
#pragma unroll
    for (int r = 0; r < 8; r++) { acc[r][0] = 0ULL; acc[r][1] = 0ULL; }

    for (int k0 = 0; k0 < FIN; k0 += 32) {
        {
            const int rr = t >> 3, cc = (t & 7) * 4;
            float4 v0 = *reinterpret_cast<const float4*>(&x[(size_t)(row0 + rr) * FIN + k0 + cc]);
            float4 v1 = *reinterpret_cast<const float4*>(&x[(size_t)(row0 + rr + 32) * FIN + k0 + cc]);
            *reinterpret_cast<float4*>(&xs[rr][cc]) = v0;
            *reinterpret_cast<float4*>(&xs[rr + 32][cc]) = v1;
        }
        {
            const int kr = t >> 5, cc = (t & 31) * 4;
#pragma unroll
            for (int i = 0; i < 4; i++) {
                float4 v = *reinterpret_cast<const float4*>(&W[(size_t)(k0 + kr + i * 8) * FOUT + cc]);
                *reinterpret_cast<float4*>(&ws[kr + i * 8][cc]) = v;
            }
        }
        __syncthreads();
#pragma unroll
        for (int k = 0; k < 32; k++) {
            ulonglong2 wv = *reinterpret_cast<const ulonglong2*>(&ws[k][c4]);
#pragma unroll
            for (int r = 0; r < 8; r++) {
                float xv = xs[rg * 8 + r][k];
                unsigned long long xd = pk2(xv, xv);
                acc[r][0] = ffma2(xd, wv.x, acc[r][0]);
                acc[r][1] = ffma2(xd, wv.y, acc[r][1]);
            }
        }
        __syncthreads();
    }

    float4 a1 = *reinterpret_cast<const float4*>(&a[c4]);
    float4 a2 = *reinterpret_cast<const float4*>(&a[FOUT + c4]);
#pragma unroll
    for (int r = 0; r < 8; r++) {
        float h0, h1, h2, h3;
        upk2(acc[r][0], h0, h1);
        upk2(acc[r][1], h2, h3);
        const int grow = row0 + rg * 8 + r;
        unsigned hi01, hi23, lo01, lo23;
        CVT_BF16X2(hi01, h0, h1);
        CVT_BF16X2(hi23, h2, h3);
        float q0 = __uint_as_float(hi01 << 16);
        float q1 = __uint_as_float(hi01 & 0xffff0000u);
        float q2 = __uint_as_float(hi23 << 16);
        float q3 = __uint_as_float(hi23 & 0xffff0000u);
        CVT_BF16X2(lo01, h0 - q0, h1 - q1);
        CVT_BF16X2(lo23, h2 - q2, h3 - q3);
        *reinterpret_cast<uint2*>(&g_hh[(size_t)grow * 64 + (c4 >> 1)]) = make_uint2(hi01, hi23);
        *reinterpret_cast<uint2*>(&g_hl[(size_t)grow * 64 + (c4 >> 1)]) = make_uint2(lo01, lo23);

        float s1 = h0 * a1.x + h1 * a1.y + h2 * a1.z + h3 * a1.w;
        float s2 = h0 * a2.x + h1 * a2.y + h2 * a2.z + h3 * a2.w;
#pragma unroll
        for (int off = 16; off; off >>= 1) {
            s1 += __shfl_xor_sync(0xffffffffu, s1, off);
            s2 += __shfl_xor_sync(0xffffffffu, s2, off);
        }
        if ((t & 31) == 0) { g_f1[grow] = s1; g_f2[grow] = s2; }
    }
}

// ============================================================
// Kernel 2: mma.sync (HMMA) fused attention, pipelined.
// CTA = 64 rows x 128 F, 256 thr / 8 warps; warp = m16 x n64 slab.
// ONE __syncthreads per tile (P double-buffered). adj/f2 loads for the
// next tile issue right after the sync; exp+store happen after the MMA
// loop, so DRAM latency hides under tensor work.
// ============================================================
#define JT2 64
#define NT2 (NNODE / JT2)           // 32

#define OFF_PHI 0                    // 2 bufs x 8 KB
#define OFF_PLO 16384                // 2 bufs x 8 KB
#define OFF_H   32768                // 2 bufs x 32 KB: [hi h0][hi h1][lo h0][lo h1]
#define OFF_LROW (OFF_H + 65536)     // 64 floats
#define SMEM_ATTN (OFF_LROW + 256)   // ~98.5 KB

__global__ void __launch_bounds__(256, 2) k_attn(const int* __restrict__ adj,
                                                 float* __restrict__ out) {
    extern __shared__ char smem[];
    const unsigned sb = smem_u32(smem);
    const int tid = threadIdx.x;
    const int w = tid >> 5, lane = tid & 31;
    const int b = blockIdx.y;
    const int row0 = blockIdx.x * 64;

    // ---- MMA geometry ----
    const int mrow0 = (w & 3) * 16;          // warp's m-slab (local rows)
    const int nhalf = w >> 2;                // warp's F-half (64 cols)
    const int asub = lane >> 3, ai = lane & 7;
    const int a_row = mrow0 + (asub & 1) * 8 + ai;
    const int a_kof = (asub >> 1) * 8;
    const int b_krow = (asub & 1) * 8 + ai;
    const int b_nof = (asub >> 1) * 8;

    // ---- P-gen geometry ----
    const int prow = w * 8 + (lane >> 2);    // local row this thread generates
    const int jb0 = (lane & 3) * 2;          // j within 8-col sector
    const float f1r = g_f1[b * NNODE + row0 + prow];
    const int* adjRow = adj + ((size_t)(b * NNODE + row0 + prow)) * NNODE;
    const float* f2B = g_f2 + b * NNODE;
    const char* hhB = (const char*)g_hh + (size_t)(b * NNODE) * 256;
    const char* hlB = (const char*)g_hl + (size_t)(b * NNODE) * 256;

    float acc[8][4];
#pragma unroll
    for (int i = 0; i < 8; i++)
#pragma unroll
        for (int k = 0; k < 4; k++) acc[i][k] = 0.f;
    float lpart = 0.f;

    // prefetch registers for next tile's P inputs
    uint2  av[8];
    float2 f2v[8];

    // ---- stage H (hi+lo) tile into buffer ----
    auto stage = [&](int t2) {
        const unsigned hb = sb + OFF_H + (t2 & 1) * 32768;
        const char* sh = hhB + (size_t)t2 * 64 * 256;
        const char* sl = hlB + (size_t)t2 * 64 * 256;
#pragma unroll
        for (int k = 0; k < 4; k++) {
            int idx = tid * 4 + k;           // 0..1023
            int row = idx >> 4, ch = idx & 15;
            int half = ch >> 3, c = ch & 7;
            unsigned swo = SW128((unsigned)(row * 128 + c * 16));
            unsigned dh = hb + half * 8192 + swo;
            unsigned dl = hb + 16384 + half * 8192 + swo;
            const char* gsrc = sh + row * 256 + half * 128 + c * 16;
            asm volatile("cp.async.cg.shared.global [%0], [%1], 16;" :: "r"(dh), "l"(gsrc));
            gsrc = sl + row * 256 + half * 128 + c * 16;
            asm volatile("cp.async.cg.shared.global [%0], [%1], 16;" :: "r"(dl), "l"(gsrc));
        }
        asm volatile("cp.async.commit_group;");
    };

    // ---- issue adj/f2 loads for tile t2 into registers ----
    auto pload = [&](int t2) {
        const int jg = t2 * JT2;
#pragma unroll
        for (int jj = 0; jj < 8; jj++) {
            const int jl = jb0 + jj * 8;
            f2v[jj] = *reinterpret_cast<const float2*>(f2B + jg + jl);
            av[jj]  = *reinterpret_cast<const uint2*>(adjRow + jg + jl);
        }
    };

    // ---- exp + split-bf16 store for tile t2 (consumes av/f2v) ----
    auto pstore = [&](int t2) {
        const unsigned pbuf = (t2 & 1) * 8192;
#pragma unroll
        for (int jj = 0; jj < 8; jj++) {
            const int jl = jb0 + jj * 8;
            float t1 = f1r + f2v[jj].x;
            t1 = fmaxf(t1, LRELU_ALPHA * t1);
            t1 = av[jj].x ? t1 : NEGINF;
            float t2f = f1r + f2v[jj].y;
            t2f = fmaxf(t2f, LRELU_ALPHA * t2f);
            t2f = av[jj].y ? t2f : NEGINF;
            float p1 = __expf(t1), p2 = __expf(t2f);
            lpart += p1 + p2;
            unsigned hi;
            CVT_BF16X2(hi, p1, p2);
            float q1 = __uint_as_float(hi << 16);
            float q2 = __uint_as_float(hi & 0xffff0000u);
            unsigned lo;
            CVT_BF16X2(lo, p1 - q1, p2 - q2);
            unsigned off = SW128((unsigned)(prow * 128 + jl * 2));
            asm volatile("st.shared.b32 [%0], %1;"
                         :: "r"(sb + OFF_PHI + pbuf + off), "r"(hi) : "memory");
            asm volatile("st.shared.b32 [%0], %1;"
                         :: "r"(sb + OFF_PLO + pbuf + off), "r"(lo) : "memory");
        }
    };

    // prologue: H(0) staged, P(0) built
    stage(0);
    pload(0);
    pstore(0);

    for (int t = 0; t < NT2; t++) {
        __syncthreads();                       // P(t) visible; old H buf free
        if (t + 1 < NT2) {
            stage(t + 1);                      // H prefetch into (t+1)&1
            pload(t + 1);                      // adj/f2 DRAM loads in flight
            asm volatile("cp.async.wait_group 1;");  // H(t) resident
        } else {
            asm volatile("cp.async.wait_group 0;");
        }

        const unsigned pb = (t & 1) * 8192;
        const unsigned hb = sb + OFF_H + (t & 1) * 32768 + nhalf * 8192;
#pragma unroll
        for (int ks = 0; ks < 4; ks++) {
            unsigned PAh[4], PAl[4];
            unsigned aoff = SW128((unsigned)(a_row * 128 + (ks * 16 + a_kof) * 2));
            ldsm_x4(PAh[0], PAh[1], PAh[2], PAh[3], sb + OFF_PHI + pb + aoff);
            ldsm_x4(PAl[0], PAl[1], PAl[2], PAl[3], sb + OFF_PLO + pb + aoff);
#pragma unroll
            for (int nb = 0; nb < 4; nb++) {
                unsigned Bh[4], Bl[4];
                unsigned off = SW128(
                    (unsigned)((ks * 16 + b_krow) * 128 + (nb * 16 + b_nof) * 2));
                ldsm_x4_t(Bh[0], Bh[1], Bh[2], Bh[3], hb + off);
                ldsm_x4_t(Bl[0], Bl[1], Bl[2], Bl[3], hb + 16384 + off);
                mma_bf16(acc[nb * 2],     PAh, Bh[0], Bh[1]);
                mma_bf16(acc[nb * 2 + 1], PAh, Bh[2], Bh[3]);
                mma_bf16(acc[nb * 2],     PAh, Bl[0], Bl[1]);
                mma_bf16(acc[nb * 2 + 1], PAh, Bl[2], Bl[3]);
                mma_bf16(acc[nb * 2],     PAl, Bh[0], Bh[1]);
                mma_bf16(acc[nb * 2 + 1], PAl, Bh[2], Bh[3]);
            }
        }

        if (t + 1 < NT2) pstore(t + 1);        // exp + store into other P buf
    }

    // ---- row sums: reduce 4 partials per row, publish to smem ----
#pragma unroll
    for (int off = 1; off <= 2; off <<= 1)
        lpart += __shfl_xor_sync(0xffffffffu, lpart, off);
    if ((lane & 3) == 0)
        *reinterpret_cast<float*>(smem + OFF_LROW + prow * 4) = lpart;
    __syncthreads();

    // ---- epilogue: normalize + ELU + store ----
    const int gid = lane >> 2, tig = lane & 3;
    const float inv0 = 1.0f / reinterpret_cast<float*>(smem + OFF_LROW)[mrow0 + gid];
    const float inv1 = 1.0f / reinterpret_cast<float*>(smem + OFF_LROW)[mrow0 + gid + 8];
    float* outB = out + ((size_t)(b * NNODE + row0)) * FOUT;
#pragma unroll
    for (int k = 0; k < 8; k++) {
        const int col = nhalf * 64 + (k >> 1) * 16 + (k & 1) * 8 + tig * 2;
        float v0 = acc[k][0] * inv0, v1 = acc[k][1] * inv0;
        float v2 = acc[k][2] * inv1, v3 = acc[k][3] * inv1;
        v0 = v0 > 0.f ? v0 : expm1f(v0);
        v1 = v1 > 0.f ? v1 : expm1f(v1);
        v2 = v2 > 0.f ? v2 : expm1f(v2);
        v3 = v3 > 0.f ? v3 : expm1f(v3);
        *reinterpret_cast<float2*>(&outB[(size_t)(mrow0 + gid) * FOUT + col]) =
            make_float2(v0, v1);
        *reinterpret_cast<float2*>(&outB[(size_t)(mrow0 + gid + 8) * FOUT + col]) =
            make_float2(v2, v3);
    }
}

// ============================================================
extern "C" void kernel_launch(void* const* d_in, const int* in_sizes, int n_in,
                              void* d_out, int out_size) {
    const float* x   = (const float*)d_in[0];   // (8, 2048, 256) f32
    const int*   adj = (const int*)d_in[1];     // (8, 2048, 2048) i32
    const float* W   = (const float*)d_in[2];   // (256, 128) f32
    const float* a   = (const float*)d_in[3];   // (256, 1) f32
    float* out = (float*)d_out;                 // (8, 2048, 128) f32

    cudaFuncSetAttribute(k_attn, cudaFuncAttributeMaxDynamicSharedMemorySize, SMEM_ATTN);

    k_gemm<<<(BATCH * NNODE) / 64, 256>>>(x, W, a);
    dim3 grid(NNODE / 64, BATCH);
    k_attn<<<grid, 256, SMEM_ATTN>>>(adj, out);
}